// round 10
// baseline (speedup 1.0000x reference)
#include <cuda_runtime.h>
#include <math.h>

#define N_NODES  50000
#define N_EDGES  400000
#define NCH      16
#define RCUT     10.0f
#define MAX_DEG  64
#define TOTAL_EK (N_EDGES * NCH)            // 6400000
#define OUT1_OFF (N_NODES * NCH)            // 800000
#define OUT2_OFF (N_NODES * NCH * 4)        // 3200000
#define WPB      8                          // warps (=nodes) per block

// ---- scratch (__device__ globals: no allocation allowed) ----
__device__ float  g_dist[N_EDGES];
__device__ int    g_cnt[N_NODES];                 // degree by src (zero at entry, reset by gather)
__device__ float4 g_rec4[N_NODES * MAX_DEG];      // (ux,uy,uz, dst-as-bits) bucketed by src
__device__ int    g_rece[N_NODES * MAX_DEG];      // original edge id per slot
__device__ float  g_rho[TOTAL_EK];                // rho[e*16+k], linear

// geometry + direct bucket scatter of edge records
__global__ void geom_kernel(const float* __restrict__ pos,
                            const int* __restrict__ ei) {
    int e = blockIdx.x * blockDim.x + threadIdx.x;
    if (e >= N_EDGES) return;
    int s = ei[e];
    int d = ei[N_EDGES + e];
    float rx = pos[3 * s + 0] - pos[3 * d + 0];
    float ry = pos[3 * s + 1] - pos[3 * d + 1];
    float rz = pos[3 * s + 2] - pos[3 * d + 2];
    float d2 = rx * rx + ry * ry + rz * rz;
    float inv = rsqrtf(d2);
    g_dist[e] = d2 * inv;
    int rank = atomicAdd(&g_cnt[s], 1);
    int slot = s * MAX_DEG + rank;
    g_rec4[slot] = make_float4(rx * inv, ry * inv, rz * inv, __int_as_float(d));
    g_rece[slot] = e;
}

// radial basis, faithful [K,E]->[E,K] reshape quirk; coalesced read AND write
__global__ void rho_kernel() {
    int idx = blockIdx.x * blockDim.x + threadIdx.x;
    if (idx >= TOTAL_EK) return;
    int n_idx = idx / N_EDGES;
    int e_idx = idx - n_idx * N_EDGES;
    float rr  = g_dist[e_idx];
    g_rho[idx] = 0.44721359549995794f *
                 __sinf((float)(n_idx + 1) * ((float)M_PI / RCUT) * rr) / rr;
}

// gather: ONE WARP PER NODE; half-warp h handles edges 2j+h, lanes k=0..15
// are channels. h rows staged cooperatively via smem (7 global lines/edge
// instead of 52), rho preloaded -> lean issue AND lean wavefronts.
__global__ void __launch_bounds__(256)
gather_kernel(const float* __restrict__ h0,
              const float* __restrict__ h1,
              const float* __restrict__ h2,
              float* __restrict__ out) {
    __shared__ float4 sh[WPB * 104];       // 2 edges * 52 f4 per warp

    int warpid = threadIdx.x >> 5;
    int lane   = threadIdx.x & 31;
    int half   = lane >> 4;
    int k      = lane & 15;
    int n      = blockIdx.x * WPB + warpid;   // grid covers exactly N_NODES

    int cnt = g_cnt[n];
    int off = n * MAX_DEG;

    float4* stg = sh + warpid * 104 + half * 52;
    const float* smf = (const float*)(sh + warpid * 104) + half * 208;

    float a0 = 0.0f;
    float a1x = 0.0f, a1y = 0.0f, a1z = 0.0f;
    float a2[9] = {0,0,0,0,0,0,0,0,0};

    int jmax = (cnt + 1) >> 1;
    for (int j = 0; j < jmax; ++j) {
        int idx2 = 2 * j + half;
        bool valid = idx2 < cnt;
        int slot = off + (valid ? idx2 : 0);

        float4 rec = g_rec4[slot];             // broadcast within half-warp
        int    e   = g_rece[slot];
        int dst = __float_as_int(rec.w);
        float ux = rec.x, uy = rec.y, uz = rec.z;

        float rho = 0.0f;
        if (valid) rho = __ldg(g_rho + e * NCH + k);   // 64B contiguous per half

        // ---- cooperative staging: this half's edge row, 52 f4 = 832B ----
        const float4* H0 = (const float4*)(h0 + (size_t)dst * 16);
        const float4* H1 = (const float4*)(h1 + (size_t)dst * 48);
        const float4* H2 = (const float4*)(h2 + (size_t)dst * 144);
        stg[k]      = __ldg(k < 4 ? H0 + k : H1 + (k - 4));
        stg[16 + k] = __ldg(H2 + k);
        stg[32 + k] = __ldg(H2 + 16 + k);
        if (k < 4) stg[48 + k] = __ldg(H2 + 32 + k);
        __syncwarp();

        // ---- per-channel smem reads (bank-conflict-free, verified) ----
        float s  = smf[k];
        float vx = smf[16 + 3 * k], vy = smf[17 + 3 * k], vz = smf[18 + 3 * k];
        const float* Mp = smf + 64 + 9 * k;
        float M00 = Mp[0], M01 = Mp[1], M02 = Mp[2];
        float M10 = Mp[3], M11 = Mp[4], M12 = Mp[5];
        float M20 = Mp[6], M21 = Mp[7], M22 = Mp[8];

        float vd = vx * ux + vy * uy + vz * uz;
        float tr = M00 + M11 + M22;
        float Mux  = M00 * ux + M01 * uy + M02 * uz;
        float Muy  = M10 * ux + M11 * uy + M12 * uz;
        float Muz  = M20 * ux + M21 * uy + M22 * uz;
        float Mtux = M00 * ux + M10 * uy + M20 * uz;
        float Mtuy = M01 * ux + M11 * uy + M21 * uz;
        float Mtuz = M02 * ux + M12 * uy + M22 * uz;
        float uMu  = ux * Mux + uy * Muy + uz * Muz;

        a0 += rho * (2.0f * s + vd + 2.0f * tr + 2.0f * uMu);

        float c1 = rho * (s + 2.0f * vd + tr);
        a1x += c1 * ux + rho * (2.0f * vx + Mux + Mtux);
        a1y += c1 * uy + rho * (2.0f * vy + Muy + Mtuy);
        a1z += c1 * uz + rho * (2.0f * vz + Muz + Mtuz);

        float ct = rho * (s + tr);
        float ax = ct * ux + rho * (vx + 2.0f * (Mux + Mtux));
        float ay = ct * uy + rho * (vy + 2.0f * (Muy + Mtuy));
        float az = ct * uz + rho * (vz + 2.0f * (Muz + Mtuz));
        float r2m = 2.0f * rho;
        a2[0] += r2m * M00 + ax * ux;
        a2[1] += r2m * M01 + ax * uy;
        a2[2] += r2m * M02 + ax * uz;
        a2[3] += r2m * M10 + ay * ux;
        a2[4] += r2m * M11 + ay * uy;
        a2[5] += r2m * M12 + ay * uz;
        a2[6] += r2m * M20 + az * ux;
        a2[7] += r2m * M21 + az * uy;
        a2[8] += r2m * M22 + az * uz;

        __syncwarp();                        // staging region reusable
    }

    // merge the two half-warps (same channels, disjoint edges)
    const unsigned FULL = 0xffffffffu;
    a0  += __shfl_xor_sync(FULL, a0, 16);
    a1x += __shfl_xor_sync(FULL, a1x, 16);
    a1y += __shfl_xor_sync(FULL, a1y, 16);
    a1z += __shfl_xor_sync(FULL, a1z, 16);
    #pragma unroll
    for (int j = 0; j < 9; ++j) a2[j] += __shfl_xor_sync(FULL, a2[j], 16);

    // staged output: per-channel layout in smem, then coalesced f4 stores
    float* w = (float*)(sh + warpid * 104);
    if (half == 0) {
        w[k] = a0;
        w[16 + 3 * k] = a1x; w[17 + 3 * k] = a1y; w[18 + 3 * k] = a1z;
        float* mw = w + 64 + 9 * k;
        #pragma unroll
        for (int j = 0; j < 9; ++j) mw[j] = a2[j];
    }
    __syncwarp();

    const float4* rd = sh + warpid * 104;     // 52 f4 = {out0row, out1row, out2row}
    float4* O0 = (float4*)(out + (size_t)n * 16);
    float4* O1 = (float4*)(out + OUT1_OFF + (size_t)n * 48);
    float4* O2 = (float4*)(out + OUT2_OFF + (size_t)n * 144);
    {
        float4 val = rd[lane];
        float4* p = (lane < 4) ? (O0 + lane)
                  : ((lane < 16) ? (O1 + lane - 4) : (O2 + lane - 16));
        *p = val;
    }
    {
        int t = lane + 32;                     // 32..51
        if (t < 52) O2[t - 16] = rd[t];
    }

    if (lane == 0) g_cnt[n] = 0;               // reset for next launch
}

extern "C" void kernel_launch(void* const* d_in, const int* in_sizes, int n_in,
                              void* d_out, int out_size) {
    const float* h0  = (const float*)d_in[0];
    const float* h1  = (const float*)d_in[1];
    const float* h2  = (const float*)d_in[2];
    const float* pos = (const float*)d_in[3];
    // d_in[4] = channel_weights (provably unused by reference output)
    const int*   ei  = (const int*)d_in[5];
    float* out = (float*)d_out;

    geom_kernel<<<(N_EDGES + 255) / 256, 256>>>(pos, ei);
    rho_kernel<<<(TOTAL_EK + 255) / 256, 256>>>();
    gather_kernel<<<N_NODES / WPB, 32 * WPB>>>(h0, h1, h2, out);
}

// round 11
// speedup vs baseline: 1.1774x; 1.1774x over previous
#include <cuda_runtime.h>
#include <math.h>

#define N_NODES  50000
#define N_EDGES  400000
#define NCH      16
#define RCUT     10.0f
#define MAX_DEG  64
#define TOTAL_NK (N_NODES * NCH)            // 800000
#define OUT1_OFF (N_NODES * NCH)            // 800000
#define OUT2_OFF (N_NODES * NCH * 4)        // 3200000
#define WPB      8                          // warps (=nodes) per block
#define NCOMP    13                         // s, v(3), M(9)

// ---- scratch (__device__ globals: no allocation allowed) ----
__device__ float  g_dist[N_EDGES];
__device__ int    g_cnt[N_NODES];                 // degree by src (zero at entry, reset by gather)
__device__ float4 g_rec4[N_NODES * MAX_DEG];      // (ux,uy,uz, dst-as-bits) bucketed by src
__device__ int    g_rece[N_NODES * MAX_DEG];      // original edge id per slot
__device__ float  g_hp[N_NODES * NCOMP * NCH];    // h transposed: [n][component][k]

// geometry + direct bucket scatter of edge records
__global__ void geom_kernel(const float* __restrict__ pos,
                            const int* __restrict__ ei) {
    int e = blockIdx.x * blockDim.x + threadIdx.x;
    if (e >= N_EDGES) return;
    int s = ei[e];
    int d = ei[N_EDGES + e];
    float rx = pos[3 * s + 0] - pos[3 * d + 0];
    float ry = pos[3 * s + 1] - pos[3 * d + 1];
    float rz = pos[3 * s + 2] - pos[3 * d + 2];
    float d2 = rx * rx + ry * ry + rz * rz;
    float inv = rsqrtf(d2);
    g_dist[e] = d2 * inv;
    int rank = atomicAdd(&g_cnt[s], 1);
    int slot = s * MAX_DEG + rank;
    g_rec4[slot] = make_float4(rx * inv, ry * inv, rz * inv, __int_as_float(d));
    g_rece[slot] = e;
}

// transpose h into per-component-contiguous-channel layout:
// g_hp[(n*13 + c)*16 + k];  c: 0=s, 1..3=v, 4..12=M
__global__ void pack_kernel(const float* __restrict__ h0,
                            const float* __restrict__ h1,
                            const float* __restrict__ h2) {
    int idx = blockIdx.x * blockDim.x + threadIdx.x;
    if (idx >= TOTAL_NK) return;
    int n = idx >> 4;
    int k = idx & 15;
    float* o = g_hp + (n * NCOMP) * NCH + k;
    o[0] = h0[idx];
    const float* vp = h1 + (size_t)idx * 3;
    o[1 * NCH] = vp[0];
    o[2 * NCH] = vp[1];
    o[3 * NCH] = vp[2];
    const float* Mp = h2 + (size_t)idx * 9;
    #pragma unroll
    for (int c = 0; c < 9; ++c) o[(4 + c) * NCH] = Mp[c];
}

// gather: ONE WARP PER NODE; half-warp h handles edges 2j+h, lanes k=0..15 are
// channels. Packed h rows -> every LDG is lane-contiguous (1 line per edge).
__global__ void __launch_bounds__(256)
gather_kernel(float* __restrict__ out) {
    __shared__ float4 sh[WPB * 52];        // epilogue staging only

    int warpid = threadIdx.x >> 5;
    int lane   = threadIdx.x & 31;
    int half   = lane >> 4;
    int k      = lane & 15;
    int n      = blockIdx.x * WPB + warpid;   // grid covers exactly N_NODES

    int cnt = g_cnt[n];
    int off = n * MAX_DEG;

    float a0 = 0.0f;
    float a1x = 0.0f, a1y = 0.0f, a1z = 0.0f;
    float a2[9] = {0,0,0,0,0,0,0,0,0};

    int jmax = (cnt + 1) >> 1;
    for (int j = 0; j < jmax; ++j) {
        int idx2 = 2 * j + half;
        bool valid = idx2 < cnt;
        int slot = off + (valid ? idx2 : 0);

        float4 rec = g_rec4[slot];             // broadcast within half-warp
        int    e   = g_rece[slot];
        int dst = __float_as_int(rec.w);
        float ux = rec.x, uy = rec.y, uz = rec.z;

        // inline radial (faithful [K,E]->[E,K] reshape quirk)
        unsigned flat  = (unsigned)e * NCH + k;
        unsigned n_idx = flat / N_EDGES;                  // magic-multiply div
        unsigned e_idx = flat - n_idx * N_EDGES;
        float rr  = __ldg(g_dist + e_idx);                // 16 consecutive floats
        float rho = valid ? (0.44721359549995794f *
                    __sinf((float)(n_idx + 1) * ((float)M_PI / RCUT) * rr) / rr)
                          : 0.0f;

        // packed h row: 13 LDGs, each 64B contiguous across the half-warp
        const float* hp = g_hp + (size_t)(dst * NCOMP) * NCH + k;
        float s  = __ldg(hp);
        float vx = __ldg(hp + 1 * NCH), vy = __ldg(hp + 2 * NCH), vz = __ldg(hp + 3 * NCH);
        float M00 = __ldg(hp + 4 * NCH), M01 = __ldg(hp + 5 * NCH), M02 = __ldg(hp + 6 * NCH);
        float M10 = __ldg(hp + 7 * NCH), M11 = __ldg(hp + 8 * NCH), M12 = __ldg(hp + 9 * NCH);
        float M20 = __ldg(hp + 10 * NCH), M21 = __ldg(hp + 11 * NCH), M22 = __ldg(hp + 12 * NCH);

        float vd = vx * ux + vy * uy + vz * uz;
        float tr = M00 + M11 + M22;
        float Mux  = M00 * ux + M01 * uy + M02 * uz;
        float Muy  = M10 * ux + M11 * uy + M12 * uz;
        float Muz  = M20 * ux + M21 * uy + M22 * uz;
        float Mtux = M00 * ux + M10 * uy + M20 * uz;
        float Mtuy = M01 * ux + M11 * uy + M21 * uz;
        float Mtuz = M02 * ux + M12 * uy + M22 * uz;
        float uMu  = ux * Mux + uy * Muy + uz * Muz;

        a0 += rho * (2.0f * s + vd + 2.0f * tr + 2.0f * uMu);

        float c1 = rho * (s + 2.0f * vd + tr);
        a1x += c1 * ux + rho * (2.0f * vx + Mux + Mtux);
        a1y += c1 * uy + rho * (2.0f * vy + Muy + Mtuy);
        a1z += c1 * uz + rho * (2.0f * vz + Muz + Mtuz);

        float ct = rho * (s + tr);
        float ax = ct * ux + rho * (vx + 2.0f * (Mux + Mtux));
        float ay = ct * uy + rho * (vy + 2.0f * (Muy + Mtuy));
        float az = ct * uz + rho * (vz + 2.0f * (Muz + Mtuz));
        float r2m = 2.0f * rho;
        a2[0] += r2m * M00 + ax * ux;
        a2[1] += r2m * M01 + ax * uy;
        a2[2] += r2m * M02 + ax * uz;
        a2[3] += r2m * M10 + ay * ux;
        a2[4] += r2m * M11 + ay * uy;
        a2[5] += r2m * M12 + ay * uz;
        a2[6] += r2m * M20 + az * ux;
        a2[7] += r2m * M21 + az * uy;
        a2[8] += r2m * M22 + az * uz;
    }

    // merge the two half-warps (same channels, disjoint edges)
    const unsigned FULL = 0xffffffffu;
    a0  += __shfl_xor_sync(FULL, a0, 16);
    a1x += __shfl_xor_sync(FULL, a1x, 16);
    a1y += __shfl_xor_sync(FULL, a1y, 16);
    a1z += __shfl_xor_sync(FULL, a1z, 16);
    #pragma unroll
    for (int j = 0; j < 9; ++j) a2[j] += __shfl_xor_sync(FULL, a2[j], 16);

    // staged output: per-channel layout in smem, then coalesced f4 stores
    float* w = (float*)(sh + warpid * 52);
    if (half == 0) {
        w[k] = a0;
        w[16 + 3 * k] = a1x; w[17 + 3 * k] = a1y; w[18 + 3 * k] = a1z;
        float* mw = w + 64 + 9 * k;
        #pragma unroll
        for (int j = 0; j < 9; ++j) mw[j] = a2[j];
    }
    __syncwarp();

    const float4* rd = sh + warpid * 52;      // 52 f4 = {out0row, out1row, out2row}
    float4* O0 = (float4*)(out + (size_t)n * 16);
    float4* O1 = (float4*)(out + OUT1_OFF + (size_t)n * 48);
    float4* O2 = (float4*)(out + OUT2_OFF + (size_t)n * 144);
    {
        float4 val = rd[lane];
        float4* p = (lane < 4) ? (O0 + lane)
                  : ((lane < 16) ? (O1 + lane - 4) : (O2 + lane - 16));
        *p = val;
    }
    {
        int t = lane + 32;                     // 32..51
        if (t < 52) O2[t - 16] = rd[t];
    }

    if (lane == 0) g_cnt[n] = 0;               // reset for next launch
}

extern "C" void kernel_launch(void* const* d_in, const int* in_sizes, int n_in,
                              void* d_out, int out_size) {
    const float* h0  = (const float*)d_in[0];
    const float* h1  = (const float*)d_in[1];
    const float* h2  = (const float*)d_in[2];
    const float* pos = (const float*)d_in[3];
    // d_in[4] = channel_weights (provably unused by reference output)
    const int*   ei  = (const int*)d_in[5];
    float* out = (float*)d_out;

    geom_kernel<<<(N_EDGES + 255) / 256, 256>>>(pos, ei);
    pack_kernel<<<(TOTAL_NK + 255) / 256, 256>>>(h0, h1, h2);
    gather_kernel<<<N_NODES / WPB, 32 * WPB>>>(out);
}

// round 12
// speedup vs baseline: 1.3053x; 1.1087x over previous
#include <cuda_runtime.h>
#include <math.h>

#define N_NODES  50000
#define N_EDGES  400000
#define NCH      16
#define RCUT     10.0f
#define MAX_DEG  64
#define TOTAL_NK (N_NODES * NCH)            // 800000
#define OUT1_OFF (N_NODES * NCH)            // 800000
#define OUT2_OFF (N_NODES * NCH * 4)        // 3200000
#define WPB      8                          // warps (=nodes) per block
#define NCOMP    13                         // s, v(3), M(9)

#define GEOM_BLOCKS  1563                   // ceil(400000/256)
#define PACK_BLOCKS  3125                   // 800000/256

// ---- scratch (__device__ globals: no allocation allowed) ----
__device__ float  g_dist[N_EDGES];
__device__ int    g_cnt[N_NODES];                 // degree by src (zero at entry, reset by gather)
__device__ float4 g_rec4[N_NODES * MAX_DEG];      // (ux,uy,uz, dst-as-bits) bucketed by src
__device__ int    g_rece[N_NODES * MAX_DEG];      // original edge id per slot
__device__ float  g_hp[N_NODES * NCOMP * NCH];    // h transposed: [n][component][k]

// fused prep: blocks [0, GEOM_BLOCKS) do geometry+bucketing,
//             blocks [GEOM_BLOCKS, GEOM_BLOCKS+PACK_BLOCKS) transpose h.
__global__ void prep_kernel(const float* __restrict__ pos,
                            const int* __restrict__ ei,
                            const float* __restrict__ h0,
                            const float* __restrict__ h1,
                            const float* __restrict__ h2) {
    if (blockIdx.x < GEOM_BLOCKS) {
        int e = blockIdx.x * blockDim.x + threadIdx.x;
        if (e >= N_EDGES) return;
        int s = ei[e];
        int d = ei[N_EDGES + e];
        float rx = pos[3 * s + 0] - pos[3 * d + 0];
        float ry = pos[3 * s + 1] - pos[3 * d + 1];
        float rz = pos[3 * s + 2] - pos[3 * d + 2];
        float d2 = rx * rx + ry * ry + rz * rz;
        float inv = rsqrtf(d2);
        g_dist[e] = d2 * inv;
        int rank = atomicAdd(&g_cnt[s], 1);
        int slot = s * MAX_DEG + rank;
        g_rec4[slot] = make_float4(rx * inv, ry * inv, rz * inv, __int_as_float(d));
        g_rece[slot] = e;
    } else {
        int idx = (blockIdx.x - GEOM_BLOCKS) * blockDim.x + threadIdx.x;
        if (idx >= TOTAL_NK) return;
        int n = idx >> 4;
        int k = idx & 15;
        float* o = g_hp + (n * NCOMP) * NCH + k;
        o[0] = h0[idx];
        const float* vp = h1 + (size_t)idx * 3;
        o[1 * NCH] = vp[0];
        o[2 * NCH] = vp[1];
        o[3 * NCH] = vp[2];
        const float* Mp = h2 + (size_t)idx * 9;
        #pragma unroll
        for (int c = 0; c < 9; ++c) o[(4 + c) * NCH] = Mp[c];
    }
}

// gather: ONE WARP PER NODE; half-warp h handles edges 2j+h, lanes k=0..15 are
// channels. Packed h rows -> every LDG is lane-contiguous. Occupancy-tuned.
__global__ void __launch_bounds__(256, 5)
gather_kernel(float* __restrict__ out) {
    __shared__ float4 sh[WPB * 52];        // epilogue staging only

    int warpid = threadIdx.x >> 5;
    int lane   = threadIdx.x & 31;
    int half   = lane >> 4;
    int k      = lane & 15;
    int n      = blockIdx.x * WPB + warpid;   // grid covers exactly N_NODES

    int cnt = g_cnt[n];
    int off = n * MAX_DEG;

    float a0 = 0.0f;
    float a1x = 0.0f, a1y = 0.0f, a1z = 0.0f;
    float a2[9] = {0,0,0,0,0,0,0,0,0};

    int jmax = (cnt + 1) >> 1;
    for (int j = 0; j < jmax; ++j) {
        int idx2 = 2 * j + half;
        bool valid = idx2 < cnt;
        int slot = off + (valid ? idx2 : 0);

        float4 rec = __ldg(&g_rec4[slot]);     // broadcast within half-warp
        int    e   = __ldg(&g_rece[slot]);
        int dst = __float_as_int(rec.w);
        float ux = rec.x, uy = rec.y, uz = rec.z;

        // packed h row: 13 LDGs, all independent, issued back-to-back
        const float* hp = g_hp + (size_t)(dst * NCOMP) * NCH + k;
        float s   = __ldg(hp);
        float vx  = __ldg(hp + 1 * NCH),  vy  = __ldg(hp + 2 * NCH),  vz  = __ldg(hp + 3 * NCH);
        float M00 = __ldg(hp + 4 * NCH),  M01 = __ldg(hp + 5 * NCH),  M02 = __ldg(hp + 6 * NCH);
        float M10 = __ldg(hp + 7 * NCH),  M11 = __ldg(hp + 8 * NCH),  M12 = __ldg(hp + 9 * NCH);
        float M20 = __ldg(hp + 10 * NCH), M21 = __ldg(hp + 11 * NCH), M22 = __ldg(hp + 12 * NCH);

        // inline radial (faithful [K,E]->[E,K] reshape quirk) overlaps the loads
        unsigned flat  = (unsigned)e * NCH + k;
        unsigned n_idx = flat / N_EDGES;                  // magic-multiply div
        unsigned e_idx = flat - n_idx * N_EDGES;
        float rr  = __ldg(g_dist + e_idx);                // 16 consecutive floats
        float rho = valid ? (0.44721359549995794f *
                    __sinf((float)(n_idx + 1) * ((float)M_PI / RCUT) * rr) / rr)
                          : 0.0f;

        float vd = vx * ux + vy * uy + vz * uz;
        float tr = M00 + M11 + M22;
        float Mux  = M00 * ux + M01 * uy + M02 * uz;
        float Muy  = M10 * ux + M11 * uy + M12 * uz;
        float Muz  = M20 * ux + M21 * uy + M22 * uz;
        float Mtux = M00 * ux + M10 * uy + M20 * uz;
        float Mtuy = M01 * ux + M11 * uy + M21 * uz;
        float Mtuz = M02 * ux + M12 * uy + M22 * uz;
        float uMu  = ux * Mux + uy * Muy + uz * Muz;

        a0 += rho * (2.0f * s + vd + 2.0f * tr + 2.0f * uMu);

        float c1 = rho * (s + 2.0f * vd + tr);
        a1x += c1 * ux + rho * (2.0f * vx + Mux + Mtux);
        a1y += c1 * uy + rho * (2.0f * vy + Muy + Mtuy);
        a1z += c1 * uz + rho * (2.0f * vz + Muz + Mtuz);

        float ct = rho * (s + tr);
        float ax = ct * ux + rho * (vx + 2.0f * (Mux + Mtux));
        float ay = ct * uy + rho * (vy + 2.0f * (Muy + Mtuy));
        float az = ct * uz + rho * (vz + 2.0f * (Muz + Mtuz));
        float r2m = 2.0f * rho;
        a2[0] += r2m * M00 + ax * ux;
        a2[1] += r2m * M01 + ax * uy;
        a2[2] += r2m * M02 + ax * uz;
        a2[3] += r2m * M10 + ay * ux;
        a2[4] += r2m * M11 + ay * uy;
        a2[5] += r2m * M12 + ay * uz;
        a2[6] += r2m * M20 + az * ux;
        a2[7] += r2m * M21 + az * uy;
        a2[8] += r2m * M22 + az * uz;
    }

    // merge the two half-warps (same channels, disjoint edges)
    const unsigned FULL = 0xffffffffu;
    a0  += __shfl_xor_sync(FULL, a0, 16);
    a1x += __shfl_xor_sync(FULL, a1x, 16);
    a1y += __shfl_xor_sync(FULL, a1y, 16);
    a1z += __shfl_xor_sync(FULL, a1z, 16);
    #pragma unroll
    for (int j = 0; j < 9; ++j) a2[j] += __shfl_xor_sync(FULL, a2[j], 16);

    // staged output: per-channel layout in smem, then coalesced f4 stores
    float* w = (float*)(sh + warpid * 52);
    if (half == 0) {
        w[k] = a0;
        w[16 + 3 * k] = a1x; w[17 + 3 * k] = a1y; w[18 + 3 * k] = a1z;
        float* mw = w + 64 + 9 * k;
        #pragma unroll
        for (int j = 0; j < 9; ++j) mw[j] = a2[j];
    }
    __syncwarp();

    const float4* rd = sh + warpid * 52;      // 52 f4 = {out0row, out1row, out2row}
    float4* O0 = (float4*)(out + (size_t)n * 16);
    float4* O1 = (float4*)(out + OUT1_OFF + (size_t)n * 48);
    float4* O2 = (float4*)(out + OUT2_OFF + (size_t)n * 144);
    {
        float4 val = rd[lane];
        float4* p = (lane < 4) ? (O0 + lane)
                  : ((lane < 16) ? (O1 + lane - 4) : (O2 + lane - 16));
        *p = val;
    }
    {
        int t = lane + 32;                     // 32..51
        if (t < 52) O2[t - 16] = rd[t];
    }

    if (lane == 0) g_cnt[n] = 0;               // reset for next launch
}

extern "C" void kernel_launch(void* const* d_in, const int* in_sizes, int n_in,
                              void* d_out, int out_size) {
    const float* h0  = (const float*)d_in[0];
    const float* h1  = (const float*)d_in[1];
    const float* h2  = (const float*)d_in[2];
    const float* pos = (const float*)d_in[3];
    // d_in[4] = channel_weights (provably unused by reference output)
    const int*   ei  = (const int*)d_in[5];
    float* out = (float*)d_out;

    prep_kernel<<<GEOM_BLOCKS + PACK_BLOCKS, 256>>>(pos, ei, h0, h1, h2);
    gather_kernel<<<N_NODES / WPB, 32 * WPB>>>(out);
}